// round 13
// baseline (speedup 1.0000x reference)
#include <cuda_runtime.h>
#include <cuda_bf16.h>
#include <math.h>

// Problem constants
#define B_   4
#define C_   128
#define H_   64
#define W_   64
#define OUT_ 128
#define LK   25

typedef unsigned int uint;
typedef unsigned long long u64;

// ---------------------------------------------------------------------------
// Device scratch: bf16-split MMA A-fragments
// ---------------------------------------------------------------------------
__device__ uint4 g_w1f[288 * 32];   // conv: F=(((c32*9+tap)*2+ks16)*2+mt)*2+split
__device__ uint4 g_w2f[128 * 32];   // z:    F=(mt*8+ks)*2+split

__device__ __forceinline__ uint cvt2(float hi_src, float lo_src) {
    uint r;
    asm("cvt.rn.bf16x2.f32 %0, %1, %2;" : "=r"(r) : "f"(hi_src), "f"(lo_src));
    return r;
}
__device__ __forceinline__ float uaf(uint u) { return __uint_as_float(u); }

__device__ __forceinline__ void split2(float f0, float f1, uint& hw, uint& lw) {
    hw = cvt2(f1, f0);
    float h0 = uaf(hw << 16);
    float h1 = uaf(hw & 0xFFFF0000u);
    lw = cvt2(f1 - h1, f0 - h0);
}

__device__ __forceinline__ void mma4(float* d, uint4 A, uint b0, uint b1) {
    asm("mma.sync.aligned.m16n8k16.row.col.f32.bf16.bf16.f32 "
        "{%0,%1,%2,%3}, {%4,%5,%6,%7}, {%8,%9}, {%0,%1,%2,%3};"
        : "+f"(d[0]), "+f"(d[1]), "+f"(d[2]), "+f"(d[3])
        : "r"(A.x), "r"(A.y), "r"(A.z), "r"(A.w), "r"(b0), "r"(b1));
}

// packed fp32x2 FMA: d += a*b (two independent fp32 lanes)
__device__ __forceinline__ void ffma2(u64& d, u64 a, u64 b) {
    asm("fma.rn.f32x2 %0, %1, %2, %0;" : "+l"(d) : "l"(a), "l"(b));
}
// build pair (hi(a), lo(b))
__device__ __forceinline__ u64 crossp(u64 a, u64 b) {
    u64 r;
    asm("{\n\t.reg .b32 ah, al, bh, bl;\n\t"
        "mov.b64 {al, ah}, %1;\n\t"
        "mov.b64 {bl, bh}, %2;\n\t"
        "mov.b64 %0, {ah, bl};\n\t}"
        : "=l"(r) : "l"(a), "l"(b));
    return r;
}
__device__ __forceinline__ float2 unpk(u64 v) {
    float2 r;
    asm("mov.b64 {%0, %1}, %2;" : "=f"(r.x), "=f"(r.y) : "l"(v));
    return r;
}

// ---------------------------------------------------------------------------
// Kernel 0: build A fragments, one uint4 per thread
// ---------------------------------------------------------------------------
__global__ void prep_kernel(const float* __restrict__ w1,
                            const float* __restrict__ w2) {
    int idx = blockIdx.x * blockDim.x + threadIdx.x;
    int lane = idx & 31;
    int g = lane >> 2, tig = lane & 3;
    if (idx < 9216) {
        int F = idx >> 5;
        int split = F & 1, mt = (F >> 1) & 1, ks = (F >> 2) & 1;
        int ct = F >> 3;
        int tap = ct % 9, chunk = ct / 9;
        int ty = tap / 3, tx = tap % 3;
        uint wv[4];
#pragma unroll
        for (int r = 0; r < 4; r++) {
            int row = g + 8 * (r & 1), col = 2 * tig + 8 * (r >> 1);
            int m  = mt * 16 + row;
            int c0 = chunk * 32 + ks * 16 + col;
            float f0 = 0.f, f1 = 0.f;
            if (m < LK) {
                f0 = w1[((m * C_ + c0) * 3 + ty) * 3 + tx];
                f1 = w1[((m * C_ + c0 + 1) * 3 + ty) * 3 + tx];
            }
            uint hw, lw; split2(f0, f1, hw, lw);
            wv[r] = split ? lw : hw;
        }
        g_w1f[F * 32 + lane] = make_uint4(wv[0], wv[1], wv[2], wv[3]);
    }
    if (idx < 4096) {
        int F = idx >> 5;
        int split = F & 1, ks = (F >> 1) & 7, mt = F >> 4;
        uint wv[4];
#pragma unroll
        for (int r = 0; r < 4; r++) {
            int row = g + 8 * (r & 1), col = 2 * tig + 8 * (r >> 1);
            int o  = mt * 16 + row;
            int c0 = ks * 16 + col;
            float4 p0 = ((const float4*)w2)[o * 128 + c0];
            float4 p1 = ((const float4*)w2)[o * 128 + c0 + 1];
            float f0 = p0.x + p0.y + p0.z + p0.w;
            float f1 = p1.x + p1.y + p1.z + p1.w;
            uint hw, lw; split2(f0, f1, hw, lw);
            wv[r] = split ? lw : hw;
        }
        g_w2f[F * 32 + lane] = make_uint4(wv[0], wv[1], wv[2], wv[3]);
    }
}

// ---------------------------------------------------------------------------
// Fused kernel. 256 threads, 2 blocks/SM.
// conv warps: kQ = wid&3 (16-ch K slice), btH = wid>>2 (4 octets, BOTH mt)
// z    warps: pxH = wid&1 (4 B-octets),  mtF = wid>>1 (2 mt tiles)
// smem: xs 18432 f | red 8448 f (xsp4 overlays; ysp4 overlays after softmax) |
//       sk 1650 f   => 114120 B, 2 blocks/SM
// ---------------------------------------------------------------------------
#define F_XS    (C_ * 144)
#define W_RED   (4 * 64 * 33)        // 8448  (= 2112 uint4, exactly fits ysp)
#define F_SK    (25 * 66)
#define SM_TOT  ((F_XS + W_RED + F_SK) * 4)

__global__ void __launch_bounds__(256, 2)
fused_kernel(const float* __restrict__ x, const float* __restrict__ b1,
             const float* __restrict__ b2, float* __restrict__ out) {
    extern __shared__ float sm[];
    float* xs   = sm;
    uint4* xsp4 = (uint4*)(sm + F_XS);        // conv B staging (overlay of red)
    float* red  = sm + F_XS;
    float* sk   = sm + F_XS + W_RED;
    uint4* ysp4 = (uint4*)(sm + F_XS);        // y staging (red region, post-softmax)

    int tid = threadIdx.x;
    int blk = blockIdx.x;
    int b   = blk >> 6;
    int t   = blk & 63;
    int h0  = (t >> 3) * 8;
    int w0  = (t & 7) * 8;
    const float* xb = x + b * C_ * H_ * W_;

    // ---- load x tile (halo 2, zero pad) via float2 ----
    for (int i = tid; i < C_ * 72; i += 256) {
        int c   = i / 72;
        int rem = i - c * 72;
        int yy  = rem / 6;
        int xx  = (rem - yy * 6) * 2;
        int h = h0 - 2 + yy, w = w0 - 2 + xx;
        float2 v = make_float2(0.f, 0.f);
        if ((unsigned)h < H_ && (unsigned)w < W_)
            v = *(const float2*)(xb + (c * H_ + h) * W_ + w);
        *(float2*)(xs + c * 144 + yy * 12 + xx) = v;
    }

    int wid = tid >> 5, lane = tid & 31;
    int g = lane >> 2, tig = lane & 3;
    int kQ = wid & 3, btH = wid >> 2;

    // ---- conv1: K-split (kQ), warp covers 2 mt x 4 octets ----
    float dc[4][2][4];
#pragma unroll
    for (int bt = 0; bt < 4; bt++)
#pragma unroll
        for (int mt = 0; mt < 2; mt++)
#pragma unroll
            for (int q = 0; q < 4; q++) dc[bt][mt][q] = 0.f;

#pragma unroll
    for (int chunk = 0; chunk < 2; chunk++) {
        __syncthreads();
        for (int i = tid; i < 1600; i += 256) {
            int pos = i % 100;
            int kc  = i / 100;            // ksl*4 + cpq
            int cpq = kc & 3, ksl = kc >> 2;
            int sy = pos / 10, sx = pos - sy * 10;
            int cb = chunk * 64 + (ksl * 8 + cpq) * 2;
            const float* xp = xs + (sy + 1) * 12 + sx + 1;
            float f0 = xp[cb * 144],        f1 = xp[(cb + 1) * 144];
            float f2 = xp[(cb + 8) * 144],  f3 = xp[(cb + 9) * 144];
            uint h0w, l0w, h1w, l1w;
            split2(f0, f1, h0w, l0w);
            split2(f2, f3, h1w, l1w);
            xsp4[(ksl * 100 + pos) * 4 + cpq] = make_uint4(h0w, h1w, l0w, l1w);
        }
        __syncthreads();

        int c32  = chunk * 2 + (kQ >> 1);
        int ks16 = kQ & 1;
#pragma unroll
        for (int tap = 0; tap < 9; tap++) {
            int ty = tap / 3, tx = tap - ty * 3;
            int F0 = (((c32 * 9 + tap) * 2 + ks16) * 2 + 0) * 2;
            int F1 = F0 + 2;
            uint4 Ah0 = g_w1f[F0 * 32 + lane];
            uint4 Al0 = g_w1f[(F0 + 1) * 32 + lane];
            uint4 Ah1 = g_w1f[F1 * 32 + lane];
            uint4 Al1 = g_w1f[(F1 + 1) * 32 + lane];
#pragma unroll
            for (int bt = 0; bt < 4; bt++) {
                int oct = btH * 4 + bt;
                uint4 q = xsp4[(kQ * 100 + (oct + ty) * 10 + g + tx) * 4 + tig];
                mma4(dc[bt][0], Ah0, q.x, q.y);
                mma4(dc[bt][0], Ah0, q.z, q.w);
                mma4(dc[bt][0], Al0, q.x, q.y);
                mma4(dc[bt][1], Ah1, q.x, q.y);
                mma4(dc[bt][1], Ah1, q.z, q.w);
                mma4(dc[bt][1], Al1, q.x, q.y);
            }
        }
    }

    __syncthreads();                    // xsp dead -> red overlay
    {
        float* rp = red + kQ * 2112;
#pragma unroll
        for (int bt = 0; bt < 4; bt++) {
            int px = (btH * 4 + bt) * 8 + 2 * tig;
#pragma unroll
            for (int mt = 0; mt < 2; mt++) {
                int m0 = mt * 16 + g;
                rp[px * 33 + m0]           = dc[bt][mt][0];
                rp[(px + 1) * 33 + m0]     = dc[bt][mt][1];
                rp[px * 33 + m0 + 8]       = dc[bt][mt][2];
                rp[(px + 1) * 33 + m0 + 8] = dc[bt][mt][3];
            }
        }
    }
    __syncthreads();

    // ---- softmax: 4 threads per pixel, shfl reductions ----
    {
        int p = tid >> 2, part = tid & 3;
        int k0 = (part == 0) ? 0 : 1 + part * 6;     // 0,7,13,19
        int kn = (part == 0) ? 7 : 6;
        float s[7];
        float m = -1e30f;
#pragma unroll
        for (int i = 0; i < 7; i++) {
            if (i < kn) {
                int k = k0 + i;
                float v = red[p * 33 + k]
                        + red[2112 + p * 33 + k]
                        + red[4224 + p * 33 + k]
                        + red[6336 + p * 33 + k]
                        + b1[k];
                s[i] = v;
                m = fmaxf(m, v);
            }
        }
        m = fmaxf(m, __shfl_xor_sync(0xffffffffu, m, 1));
        m = fmaxf(m, __shfl_xor_sync(0xffffffffu, m, 2));
        float tot = 0.f;
#pragma unroll
        for (int i = 0; i < 7; i++)
            if (i < kn) { s[i] = __expf(s[i] - m); tot += s[i]; }
        tot += __shfl_xor_sync(0xffffffffu, tot, 1);
        tot += __shfl_xor_sync(0xffffffffu, tot, 2);
        float inv = 1.f / tot;
#pragma unroll
        for (int i = 0; i < 7; i++)
            if (i < kn) sk[(k0 + i) * 66 + p] = s[i] * inv;
    }
    __syncthreads();                    // red free -> ysp overlay after this

    // ---- y phase: packed FFMA2 over pixel pairs (bit-identical math) ----
    int pp = 8 * ((lane & 15) >> 2) + (lane >> 4) * 4 + (lane & 3);
    int cg = wid;
    int px0 = 2 * pp;
    int pyy = px0 >> 3, pxx = px0 & 7;
    u64 acc2[16];
#pragma unroll
    for (int j = 0; j < 16; j++) acc2[j] = 0ull;
    {
#pragma unroll
        for (int ky = 0; ky < 5; ky++) {
            u64 sp[5];
#pragma unroll
            for (int kx = 0; kx < 5; kx++)
                sp[kx] = *(const u64*)(sk + (ky * 5 + kx) * 66 + px0);
            const float* xrow = xs + (pyy + ky) * 12 + pxx;
#pragma unroll 4
            for (int j = 0; j < 16; j++) {
                const float* ur = xrow + (cg * 16 + j) * 144;
                u64 v01 = *(const u64*)(ur);
                u64 v23 = *(const u64*)(ur + 2);
                u64 v45 = *(const u64*)(ur + 4);
                u64 v12 = crossp(v01, v23);
                u64 v34 = crossp(v23, v45);
                ffma2(acc2[j], sp[0], v01);
                ffma2(acc2[j], sp[1], v12);
                ffma2(acc2[j], sp[2], v23);
                ffma2(acc2[j], sp[3], v34);
                ffma2(acc2[j], sp[4], v45);
            }
        }
    }
    // no sync needed: pack writes the red region (free since softmax sync)

    // ---- pack y: ysp4[cg*264 + tq*66 + px] ----
    {
#pragma unroll
        for (int tq = 0; tq < 4; tq++) {
            float2 p0 = unpk(acc2[2 * tq]);      // (ya[2tq],   yb[2tq])
            float2 p1 = unpk(acc2[2 * tq + 1]);
            float2 p8 = unpk(acc2[2 * tq + 8]);
            float2 p9 = unpk(acc2[2 * tq + 9]);
            uint h0w, l0w, h1w, l1w;
            split2(p0.x, p1.x, h0w, l0w);
            split2(p8.x, p9.x, h1w, l1w);
            ysp4[cg * 264 + tq * 66 + px0] = make_uint4(h0w, h1w, l0w, l1w);
            split2(p0.y, p1.y, h0w, l0w);
            split2(p8.y, p9.y, h1w, l1w);
            ysp4[cg * 264 + tq * 66 + px0 + 1] = make_uint4(h0w, h1w, l0w, l1w);
        }
    }
    __syncthreads();

    // ---- z phase: A reused over 4 B-octets, 2 mt per warp ----
    int pxH = wid & 1, mtF = wid >> 1;
    float dz[4][2][4];
#pragma unroll
    for (int bt = 0; bt < 4; bt++)
#pragma unroll
        for (int mi = 0; mi < 2; mi++)
#pragma unroll
            for (int q = 0; q < 4; q++) dz[bt][mi][q] = 0.f;

#pragma unroll
    for (int ks = 0; ks < 8; ks++) {
        uint4 qb[4];
#pragma unroll
        for (int bt = 0; bt < 4; bt++)
            qb[bt] = ysp4[ks * 264 + tig * 66 + (pxH * 4 + bt) * 8 + g];
#pragma unroll
        for (int mi = 0; mi < 2; mi++) {
            int F = ((mtF * 2 + mi) * 8 + ks) * 2;
            uint4 Ah = g_w2f[F * 32 + lane];
            uint4 Al = g_w2f[(F + 1) * 32 + lane];
#pragma unroll
            for (int bt = 0; bt < 4; bt++) {
                mma4(dz[bt][mi], Ah, qb[bt].x, qb[bt].y);
                mma4(dz[bt][mi], Ah, qb[bt].z, qb[bt].w);
                mma4(dz[bt][mi], Al, qb[bt].x, qb[bt].y);
            }
        }
    }

    // ---- store with x2 nearest upsample ----
    {
        int cc0 = 2 * (w0 + 2 * tig);
#pragma unroll
        for (int bt = 0; bt < 4; bt++) {
            int hh = h0 + pxH * 4 + bt;          // source pixel row
#pragma unroll
            for (int mi = 0; mi < 2; mi++) {
#pragma unroll
                for (int half = 0; half < 2; half++) {
                    int o = (mtF * 2 + mi) * 16 + g + 8 * half;
                    float bo = b2[o];
                    float z0 = dz[bt][mi][2 * half]     + bo;
                    float z1 = dz[bt][mi][2 * half + 1] + bo;
                    float4 vv = make_float4(z0, z0, z1, z1);
                    size_t rowb = ((size_t)(b * OUT_ + o) * (2 * H_) + 2 * hh) * (2 * W_) + cc0;
                    *(float4*)(out + rowb)          = vv;
                    *(float4*)(out + rowb + 2 * W_) = vv;
                }
            }
        }
    }
}

// ---------------------------------------------------------------------------
extern "C" void kernel_launch(void* const* d_in, const int* in_sizes, int n_in,
                              void* d_out, int out_size) {
    const float* x  = (const float*)d_in[0];
    const float* w1 = (const float*)d_in[1];
    const float* b1 = (const float*)d_in[2];
    const float* w2 = (const float*)d_in[3];
    const float* b2 = (const float*)d_in[4];
    float* out = (float*)d_out;

    cudaFuncSetAttribute(fused_kernel,
                         cudaFuncAttributeMaxDynamicSharedMemorySize, SM_TOT);

    prep_kernel<<<36, 256>>>(w1, w2);
    fused_kernel<<<256, 256, SM_TOT>>>(x, b1, b2, out);
}

// round 14
// speedup vs baseline: 1.1113x; 1.1113x over previous
#include <cuda_runtime.h>
#include <cuda_bf16.h>
#include <math.h>

// Problem constants
#define B_   4
#define C_   128
#define H_   64
#define W_   64
#define OUT_ 128
#define LK   25

typedef unsigned int uint;
typedef unsigned long long u64;

// ---------------------------------------------------------------------------
// Device scratch: bf16-split MMA A-fragments
// ---------------------------------------------------------------------------
__device__ uint4 g_w1f[288 * 32];   // conv: F=(((c32*9+tap)*2+ks16)*2+mt)*2+split
__device__ uint4 g_w2f[128 * 32];   // z:    F=(mt*8+ks)*2+split

__device__ __forceinline__ uint cvt2(float hi_src, float lo_src) {
    uint r;
    asm("cvt.rn.bf16x2.f32 %0, %1, %2;" : "=r"(r) : "f"(hi_src), "f"(lo_src));
    return r;
}
__device__ __forceinline__ float uaf(uint u) { return __uint_as_float(u); }

__device__ __forceinline__ void split2(float f0, float f1, uint& hw, uint& lw) {
    hw = cvt2(f1, f0);
    float h0 = uaf(hw << 16);
    float h1 = uaf(hw & 0xFFFF0000u);
    lw = cvt2(f1 - h1, f0 - h0);
}

__device__ __forceinline__ void mma4(float* d, uint4 A, uint b0, uint b1) {
    asm("mma.sync.aligned.m16n8k16.row.col.f32.bf16.bf16.f32 "
        "{%0,%1,%2,%3}, {%4,%5,%6,%7}, {%8,%9}, {%0,%1,%2,%3};"
        : "+f"(d[0]), "+f"(d[1]), "+f"(d[2]), "+f"(d[3])
        : "r"(A.x), "r"(A.y), "r"(A.z), "r"(A.w), "r"(b0), "r"(b1));
}

// packed fp32x2 FMA: d += a*b (two independent fp32 lanes)
__device__ __forceinline__ void ffma2(u64& d, u64 a, u64 b) {
    asm("fma.rn.f32x2 %0, %1, %2, %0;" : "+l"(d) : "l"(a), "l"(b));
}
// build pair (hi(a), lo(b))
__device__ __forceinline__ u64 crossp(u64 a, u64 b) {
    u64 r;
    asm("{\n\t.reg .b32 ah, al, bh, bl;\n\t"
        "mov.b64 {al, ah}, %1;\n\t"
        "mov.b64 {bl, bh}, %2;\n\t"
        "mov.b64 %0, {ah, bl};\n\t}"
        : "=l"(r) : "l"(a), "l"(b));
    return r;
}
__device__ __forceinline__ float2 unpk(u64 v) {
    float2 r;
    asm("mov.b64 {%0, %1}, %2;" : "=f"(r.x), "=f"(r.y) : "l"(v));
    return r;
}

// ---------------------------------------------------------------------------
// Kernel 0: build A fragments, one uint4 per thread
// ---------------------------------------------------------------------------
__global__ void prep_kernel(const float* __restrict__ w1,
                            const float* __restrict__ w2) {
    int idx = blockIdx.x * blockDim.x + threadIdx.x;
    int lane = idx & 31;
    int g = lane >> 2, tig = lane & 3;
    if (idx < 9216) {
        int F = idx >> 5;
        int split = F & 1, mt = (F >> 1) & 1, ks = (F >> 2) & 1;
        int ct = F >> 3;
        int tap = ct % 9, chunk = ct / 9;
        int ty = tap / 3, tx = tap % 3;
        uint wv[4];
#pragma unroll
        for (int r = 0; r < 4; r++) {
            int row = g + 8 * (r & 1), col = 2 * tig + 8 * (r >> 1);
            int m  = mt * 16 + row;
            int c0 = chunk * 32 + ks * 16 + col;
            float f0 = 0.f, f1 = 0.f;
            if (m < LK) {
                f0 = w1[((m * C_ + c0) * 3 + ty) * 3 + tx];
                f1 = w1[((m * C_ + c0 + 1) * 3 + ty) * 3 + tx];
            }
            uint hw, lw; split2(f0, f1, hw, lw);
            wv[r] = split ? lw : hw;
        }
        g_w1f[F * 32 + lane] = make_uint4(wv[0], wv[1], wv[2], wv[3]);
    }
    if (idx < 4096) {
        int F = idx >> 5;
        int split = F & 1, ks = (F >> 1) & 7, mt = F >> 4;
        uint wv[4];
#pragma unroll
        for (int r = 0; r < 4; r++) {
            int row = g + 8 * (r & 1), col = 2 * tig + 8 * (r >> 1);
            int o  = mt * 16 + row;
            int c0 = ks * 16 + col;
            float4 p0 = ((const float4*)w2)[o * 128 + c0];
            float4 p1 = ((const float4*)w2)[o * 128 + c0 + 1];
            float f0 = p0.x + p0.y + p0.z + p0.w;
            float f1 = p1.x + p1.y + p1.z + p1.w;
            uint hw, lw; split2(f0, f1, hw, lw);
            wv[r] = split ? lw : hw;
        }
        g_w2f[F * 32 + lane] = make_uint4(wv[0], wv[1], wv[2], wv[3]);
    }
}

// ---------------------------------------------------------------------------
// Fused kernel. 256 threads, 2 blocks/SM.
// conv warps: kQ = wid&3 (16-ch K slice), btH = wid>>2 (4 octets, BOTH mt)
// z    warps: pxH = wid&1 (4 B-octets),  mtF = wid>>1 (2 mt tiles)
// smem: xs 18432 f | red 8448 f (xsp4 overlays; ysp4 overlays after softmax) |
//       sk 1650 f   => 114120 B, 2 blocks/SM
// ---------------------------------------------------------------------------
#define F_XS    (C_ * 144)
#define W_RED   (4 * 64 * 33)        // 8448  (= 2112 uint4, exactly fits ysp)
#define F_SK    (25 * 66)
#define SM_TOT  ((F_XS + W_RED + F_SK) * 4)

__global__ void __launch_bounds__(256, 2)
fused_kernel(const float* __restrict__ x, const float* __restrict__ b1,
             const float* __restrict__ b2, float* __restrict__ out) {
    extern __shared__ float sm[];
    float* xs   = sm;
    uint4* xsp4 = (uint4*)(sm + F_XS);        // conv B staging (overlay of red)
    float* red  = sm + F_XS;
    float* sk   = sm + F_XS + W_RED;
    uint4* ysp4 = (uint4*)(sm + F_XS);        // y staging (red region, post-softmax)

    int tid = threadIdx.x;
    int blk = blockIdx.x;
    int b   = blk >> 6;
    int t   = blk & 63;
    int h0  = (t >> 3) * 8;
    int w0  = (t & 7) * 8;
    const float* xb = x + b * C_ * H_ * W_;

    // ---- load x tile (halo 2, zero pad) via float2 ----
    for (int i = tid; i < C_ * 72; i += 256) {
        int c   = i / 72;
        int rem = i - c * 72;
        int yy  = rem / 6;
        int xx  = (rem - yy * 6) * 2;
        int h = h0 - 2 + yy, w = w0 - 2 + xx;
        float2 v = make_float2(0.f, 0.f);
        if ((unsigned)h < H_ && (unsigned)w < W_)
            v = *(const float2*)(xb + (c * H_ + h) * W_ + w);
        *(float2*)(xs + c * 144 + yy * 12 + xx) = v;
    }

    int wid = tid >> 5, lane = tid & 31;
    int g = lane >> 2, tig = lane & 3;
    int kQ = wid & 3, btH = wid >> 2;

    // ---- conv1: K-split (kQ), warp covers 2 mt x 4 octets ----
    float dc[4][2][4];
#pragma unroll
    for (int bt = 0; bt < 4; bt++)
#pragma unroll
        for (int mt = 0; mt < 2; mt++)
#pragma unroll
            for (int q = 0; q < 4; q++) dc[bt][mt][q] = 0.f;

#pragma unroll
    for (int chunk = 0; chunk < 2; chunk++) {
        __syncthreads();
        for (int i = tid; i < 1600; i += 256) {
            int pos = i % 100;
            int kc  = i / 100;            // ksl*4 + cpq
            int cpq = kc & 3, ksl = kc >> 2;
            int sy = pos / 10, sx = pos - sy * 10;
            int cb = chunk * 64 + (ksl * 8 + cpq) * 2;
            const float* xp = xs + (sy + 1) * 12 + sx + 1;
            float f0 = xp[cb * 144],        f1 = xp[(cb + 1) * 144];
            float f2 = xp[(cb + 8) * 144],  f3 = xp[(cb + 9) * 144];
            uint h0w, l0w, h1w, l1w;
            split2(f0, f1, h0w, l0w);
            split2(f2, f3, h1w, l1w);
            xsp4[(ksl * 100 + pos) * 4 + cpq] = make_uint4(h0w, h1w, l0w, l1w);
        }
        __syncthreads();

        int c32  = chunk * 2 + (kQ >> 1);
        int ks16 = kQ & 1;
#pragma unroll
        for (int tap = 0; tap < 9; tap++) {
            int ty = tap / 3, tx = tap - ty * 3;
            int F0 = (((c32 * 9 + tap) * 2 + ks16) * 2 + 0) * 2;
            int F1 = F0 + 2;
            uint4 Ah0 = g_w1f[F0 * 32 + lane];
            uint4 Al0 = g_w1f[(F0 + 1) * 32 + lane];
            uint4 Ah1 = g_w1f[F1 * 32 + lane];
            uint4 Al1 = g_w1f[(F1 + 1) * 32 + lane];
#pragma unroll
            for (int bt = 0; bt < 4; bt++) {
                int oct = btH * 4 + bt;
                uint4 q = xsp4[(kQ * 100 + (oct + ty) * 10 + g + tx) * 4 + tig];
                mma4(dc[bt][0], Ah0, q.x, q.y);
                mma4(dc[bt][0], Ah0, q.z, q.w);
                mma4(dc[bt][0], Al0, q.x, q.y);
                mma4(dc[bt][1], Ah1, q.x, q.y);
                mma4(dc[bt][1], Ah1, q.z, q.w);
                mma4(dc[bt][1], Al1, q.x, q.y);
            }
        }
    }

    __syncthreads();                    // xsp dead -> red overlay
    {
        float* rp = red + kQ * 2112;
#pragma unroll
        for (int bt = 0; bt < 4; bt++) {
            int px = (btH * 4 + bt) * 8 + 2 * tig;
#pragma unroll
            for (int mt = 0; mt < 2; mt++) {
                int m0 = mt * 16 + g;
                rp[px * 33 + m0]           = dc[bt][mt][0];
                rp[(px + 1) * 33 + m0]     = dc[bt][mt][1];
                rp[px * 33 + m0 + 8]       = dc[bt][mt][2];
                rp[(px + 1) * 33 + m0 + 8] = dc[bt][mt][3];
            }
        }
    }
    __syncthreads();

    // ---- softmax: 4 threads per pixel, shfl reductions ----
    {
        int p = tid >> 2, part = tid & 3;
        int k0 = (part == 0) ? 0 : 1 + part * 6;     // 0,7,13,19
        int kn = (part == 0) ? 7 : 6;
        float s[7];
        float m = -1e30f;
#pragma unroll
        for (int i = 0; i < 7; i++) {
            if (i < kn) {
                int k = k0 + i;
                float v = red[p * 33 + k]
                        + red[2112 + p * 33 + k]
                        + red[4224 + p * 33 + k]
                        + red[6336 + p * 33 + k]
                        + b1[k];
                s[i] = v;
                m = fmaxf(m, v);
            }
        }
        m = fmaxf(m, __shfl_xor_sync(0xffffffffu, m, 1));
        m = fmaxf(m, __shfl_xor_sync(0xffffffffu, m, 2));
        float tot = 0.f;
#pragma unroll
        for (int i = 0; i < 7; i++)
            if (i < kn) { s[i] = __expf(s[i] - m); tot += s[i]; }
        tot += __shfl_xor_sync(0xffffffffu, tot, 1);
        tot += __shfl_xor_sync(0xffffffffu, tot, 2);
        float inv = 1.f / tot;
#pragma unroll
        for (int i = 0; i < 7; i++)
            if (i < kn) sk[(k0 + i) * 66 + p] = s[i] * inv;
    }
    __syncthreads();                    // red free -> ysp overlay after this

    // ---- y phase: packed FFMA2, TWO passes of 8 accumulators (no spills) ----
    // pass P covers channels {4P..4P+3, 8+4P..8+4P+3} -> packs tq = 2P, 2P+1
    int pp = 8 * ((lane & 15) >> 2) + (lane >> 4) * 4 + (lane & 3);
    int cg = wid;
    int px0 = 2 * pp;
    int pyy = px0 >> 3, pxx = px0 & 7;
#pragma unroll
    for (int P = 0; P < 2; P++) {
        u64 acc2[8];
#pragma unroll
        for (int al = 0; al < 8; al++) acc2[al] = 0ull;
#pragma unroll
        for (int ky = 0; ky < 5; ky++) {
            u64 sp[5];
#pragma unroll
            for (int kx = 0; kx < 5; kx++)
                sp[kx] = *(const u64*)(sk + (ky * 5 + kx) * 66 + px0);
            const float* xrow = xs + (pyy + ky) * 12 + pxx;
#pragma unroll
            for (int al = 0; al < 8; al++) {
                int j = (al < 4) ? (4 * P + al) : (8 + 4 * P + (al - 4));
                const float* ur = xrow + (cg * 16 + j) * 144;
                u64 v01 = *(const u64*)(ur);
                u64 v23 = *(const u64*)(ur + 2);
                u64 v45 = *(const u64*)(ur + 4);
                u64 v12 = crossp(v01, v23);
                u64 v34 = crossp(v23, v45);
                ffma2(acc2[al], sp[0], v01);
                ffma2(acc2[al], sp[1], v12);
                ffma2(acc2[al], sp[2], v23);
                ffma2(acc2[al], sp[3], v34);
                ffma2(acc2[al], sp[4], v45);
            }
        }
        // pack this pass's two tq groups (ysp overlays red, xs untouched)
#pragma unroll
        for (int s = 0; s < 2; s++) {
            int tq = 2 * P + s;
            float2 p0 = unpk(acc2[2 * s]);       // channel 4P+2s   (px0, px0+1)
            float2 p1 = unpk(acc2[2 * s + 1]);   // channel 4P+2s+1
            float2 p8 = unpk(acc2[4 + 2 * s]);   // channel 8+4P+2s
            float2 p9 = unpk(acc2[4 + 2 * s + 1]);
            uint h0w, l0w, h1w, l1w;
            split2(p0.x, p1.x, h0w, l0w);
            split2(p8.x, p9.x, h1w, l1w);
            ysp4[cg * 264 + tq * 66 + px0] = make_uint4(h0w, h1w, l0w, l1w);
            split2(p0.y, p1.y, h0w, l0w);
            split2(p8.y, p9.y, h1w, l1w);
            ysp4[cg * 264 + tq * 66 + px0 + 1] = make_uint4(h0w, h1w, l0w, l1w);
        }
    }
    __syncthreads();

    // ---- z phase: A reused over 4 B-octets, 2 mt per warp ----
    int pxH = wid & 1, mtF = wid >> 1;
    float dz[4][2][4];
#pragma unroll
    for (int bt = 0; bt < 4; bt++)
#pragma unroll
        for (int mi = 0; mi < 2; mi++)
#pragma unroll
            for (int q = 0; q < 4; q++) dz[bt][mi][q] = 0.f;

#pragma unroll
    for (int ks = 0; ks < 8; ks++) {
        uint4 qb[4];
#pragma unroll
        for (int bt = 0; bt < 4; bt++)
            qb[bt] = ysp4[ks * 264 + tig * 66 + (pxH * 4 + bt) * 8 + g];
#pragma unroll
        for (int mi = 0; mi < 2; mi++) {
            int F = ((mtF * 2 + mi) * 8 + ks) * 2;
            uint4 Ah = g_w2f[F * 32 + lane];
            uint4 Al = g_w2f[(F + 1) * 32 + lane];
#pragma unroll
            for (int bt = 0; bt < 4; bt++) {
                mma4(dz[bt][mi], Ah, qb[bt].x, qb[bt].y);
                mma4(dz[bt][mi], Ah, qb[bt].z, qb[bt].w);
                mma4(dz[bt][mi], Al, qb[bt].x, qb[bt].y);
            }
        }
    }

    // ---- store with x2 nearest upsample ----
    {
        int cc0 = 2 * (w0 + 2 * tig);
#pragma unroll
        for (int bt = 0; bt < 4; bt++) {
            int hh = h0 + pxH * 4 + bt;          // source pixel row
#pragma unroll
            for (int mi = 0; mi < 2; mi++) {
#pragma unroll
                for (int half = 0; half < 2; half++) {
                    int o = (mtF * 2 + mi) * 16 + g + 8 * half;
                    float bo = b2[o];
                    float z0 = dz[bt][mi][2 * half]     + bo;
                    float z1 = dz[bt][mi][2 * half + 1] + bo;
                    float4 vv = make_float4(z0, z0, z1, z1);
                    size_t rowb = ((size_t)(b * OUT_ + o) * (2 * H_) + 2 * hh) * (2 * W_) + cc0;
                    *(float4*)(out + rowb)          = vv;
                    *(float4*)(out + rowb + 2 * W_) = vv;
                }
            }
        }
    }
}

// ---------------------------------------------------------------------------
extern "C" void kernel_launch(void* const* d_in, const int* in_sizes, int n_in,
                              void* d_out, int out_size) {
    const float* x  = (const float*)d_in[0];
    const float* w1 = (const float*)d_in[1];
    const float* b1 = (const float*)d_in[2];
    const float* w2 = (const float*)d_in[3];
    const float* b2 = (const float*)d_in[4];
    float* out = (float*)d_out;

    cudaFuncSetAttribute(fused_kernel,
                         cudaFuncAttributeMaxDynamicSharedMemorySize, SM_TOT);

    prep_kernel<<<36, 256>>>(w1, w2);
    fused_kernel<<<256, 256, SM_TOT>>>(x, b1, b2, out);
}